// round 4
// baseline (speedup 1.0000x reference)
#include <cuda_runtime.h>

#define GN    6
#define NN    36
#define NB7   7            // 7x7 grid incl. trash row/col
#define NPED  8192
#define HID   128
#define RPB   128          // rows per count block
#define NSL   16           // j-slices
#define JCH   (NPED / NSL) // 512
#define HROW  (NPED / 2)   // u32 words per bin in g16 (2 rows per word)

// Global counts, u16-packed pairs of rows: g16[c*HROW + i/2] = (cnt[2q] | cnt[2q+1]<<16).
// Zero-initialized at load; embed_kernel re-zeroes after reading (replay invariant).
__device__ unsigned g16[NN * HROW];

// ---------------------------------------------------------------------------
// Phase 1: branch-free occupancy histogram. Every pair unconditionally
// increments a byte counter in a 7x7 grid; out-of-range pairs land in
// trash bins (bx==6 or by==6) that are never flushed.
// ---------------------------------------------------------------------------
__global__ __launch_bounds__(RPB) void count_kernel(const float* __restrict__ obs2) {
    __shared__ unsigned char cnt[52 * RPB];  // 49 used bins, padded
    __shared__ float2 pts[JCH];              // 4 KB

    const int t  = threadIdx.x;
    const int i  = blockIdx.x * RPB + t;
    const int j0 = blockIdx.y * JCH;

    // Stage slice points (256 float4 loads)
    {
        const float4* src = (const float4*)(obs2 + 2 * j0);
        float4* dst = (float4*)pts;
#pragma unroll
        for (int k = 0; k < JCH / 2 / RPB; k++)
            dst[t + k * RPB] = src[t + k * RPB];
    }
    // Zero counters: 52*128/4 = 1664 words
#pragma unroll
    for (int k = 0; k < 13; k++)
        ((unsigned*)cnt)[t + k * RPB] = 0u;

    const float2 pi = ((const float2*)obs2)[i];
    float nx = -pi.x, ny = -pi.y;
    unsigned long long negpi;
    asm("mov.b64 %0, {%1,%2};" : "=l"(negpi) : "f"(nx), "f"(ny));
    const unsigned long long THREE2 = 0x4040000040400000ULL;  // (3.0f, 3.0f)
    const float MAGIC = 8388608.0f;                           // 2^23

    __syncthreads();

    unsigned char* mycnt = cnt + t;

#pragma unroll 8
    for (int k = 0; k < JCH; k++) {
        const unsigned long long pj = *(const unsigned long long*)&pts[k];  // LDS.64
        unsigned long long d, e;
        // EXACT reference order: rn(pj - pi) then rn(+3), per lane
        asm("add.rn.f32x2 %0, %1, %2;" : "=l"(d) : "l"(pj), "l"(negpi));
        asm("add.rn.f32x2 %0, %1, %2;" : "=l"(e) : "l"(d), "l"(THREE2));
        const float ex = __uint_as_float((unsigned)e);
        const float ey = __uint_as_float((unsigned)(e >> 32));
        float fx, fy;
        asm("add.rm.f32 %0, %1, %2;" : "=f"(fx) : "f"(ex), "f"(MAGIC));
        asm("add.rm.f32 %0, %1, %2;" : "=f"(fy) : "f"(ey), "f"(MAGIC));
        unsigned bx = __float_as_uint(fx) - 0x4B000000u;  // floor; OOR -> huge
        unsigned by = __float_as_uint(fy) - 0x4B000000u;
        bx = umin(bx, 6u);
        by = umin(by, 6u);
        mycnt[(bx * NB7 + by) * RPB]++;   // LDS.U8/IADD/STS.U8, no predicate
    }

    __syncthreads();  // flush reads words spanning 4 threads' bytes

    // Flush the 36 valid bins: 36 bins * 32 words = 1152 u32 words, 9 per thread.
    // Word (vb, w) holds rows 4w..4w+3; RED as two u16-pair words.
#pragma unroll
    for (int k = 0; k < 9; k++) {
        const int W  = k * RPB + t;
        const int vb = W >> 5;          // valid bin 0..35
        const int w  = W & 31;
        const int bx = vb / GN, by = vb % GN;
        const unsigned v = *(const unsigned*)&cnt[(bx * NB7 + by) * RPB + 4 * w];
        if (v) {
            const unsigned lo = __byte_perm(v, 0, 0x4140);  // (b0, b1) as u16 pair
            const unsigned hi = __byte_perm(v, 0, 0x4342);  // (b2, b3)
            unsigned* dst = &g16[vb * HROW + ((blockIdx.x * RPB + 4 * w) >> 1)];
            asm volatile("red.global.add.u32 [%0], %1;" :: "l"(dst)     , "r"(lo) : "memory");
            asm volatile("red.global.add.u32 [%0], %1;" :: "l"(dst + 1), "r"(hi) : "memory");
        }
    }
}

// ---------------------------------------------------------------------------
// Phase 2: read packed counts (re-zeroing them for the next replay), remove
// the self pair (always bin 21), apply the linear embedding.
// ---------------------------------------------------------------------------
#define P2R 32
__global__ __launch_bounds__(256) void embed_kernel(const float* __restrict__ W,
                                                    const float* __restrict__ b,
                                                    float* __restrict__ out) {
    __shared__ float Ws[NN][HID];
    __shared__ float bs[HID];
    __shared__ float cs[P2R][NN];

    const int t  = threadIdx.x;
    const int i0 = blockIdx.x * P2R;

    for (int idx = t; idx < HID * NN; idx += 256)
        Ws[idx % NN][idx / NN] = W[idx];
    if (t < HID) bs[t] = b[t];

    // 36 bins x 16 words (2 rows each) = 576 words per block
    for (int idx = t; idx < NN * (P2R / 2); idx += 256) {
        const int c = idx >> 4;
        const int q = idx & 15;
        unsigned* p = &g16[c * HROW + (i0 >> 1) + q];
        const unsigned v = *p;
        *p = 0u;                          // restore zero for next replay
        const unsigned self = (c == 21) ? 1u : 0u;
        cs[2 * q + 0][c] = (float)((v & 0xFFFFu) - self);
        cs[2 * q + 1][c] = (float)((v >> 16) - self);
    }
    __syncthreads();

    const int h     = t & (HID - 1);
    const int rbase = (t >> 7) * (P2R / 2);

    float w[NN];
#pragma unroll
    for (int c = 0; c < NN; c++) w[c] = Ws[c][h];
    const float bh = bs[h];

#pragma unroll
    for (int r = 0; r < P2R / 2; r++) {
        float acc = bh;
#pragma unroll
        for (int c = 0; c < NN; c++)
            acc = fmaf(cs[rbase + r][c], w[c], acc);
        out[(i0 + rbase + r) * HID + h] = acc;
    }
}

// ---------------------------------------------------------------------------
// Inputs: 0 hidden_state (unused), 1 obs1 (unused), 2 obs2 [8192,2],
// 3 W [128,36], 4 b [128]. Output fp32 [8192,128].
// ---------------------------------------------------------------------------
extern "C" void kernel_launch(void* const* d_in, const int* in_sizes, int n_in,
                              void* d_out, int out_size) {
    const float* obs2 = (const float*)d_in[2];
    const float* W    = (const float*)d_in[3];
    const float* b    = (const float*)d_in[4];
    float*       out  = (float*)d_out;

    dim3 g1(NPED / RPB, NSL);   // 64 x 16 = 1024 blocks
    count_kernel<<<g1, RPB>>>(obs2);
    embed_kernel<<<NPED / P2R, 256>>>(W, b, out);
}

// round 5
// speedup vs baseline: 1.8891x; 1.8891x over previous
#include <cuda_runtime.h>

#define GN    6
#define NN    36
#define NB7   7            // 7x7 counter grid incl. trash row/col
#define NPED  8192
#define HID   128
#define RPB   128          // rows per count block
#define NSL   16           // j-slices
#define JCH   (NPED / NSL) // 512
#define HROW  (NPED / 2)   // u32 words per bin (2 u16 rows per word)

// Per-slice partial counts, u16-packed row pairs:
// g_part[((sl*NN)+c)*HROW + i/2] = cnt(i) | cnt(i+1)<<16.
// Fully overwritten by count_kernel every launch -> no zeroing, replay-safe.
__device__ unsigned g_part[NSL * NN * HROW];   // 9.4 MB

// ---------------------------------------------------------------------------
// Phase 1: branch-free occupancy histogram, conflict-free u32 counters.
// Every pair unconditionally increments; out-of-range lands in trash bins
// (bx==6 or by==6) which are never flushed.
// ---------------------------------------------------------------------------
__global__ __launch_bounds__(RPB) void count_kernel(const float* __restrict__ obs2) {
    __shared__ unsigned   cnt[NB7 * NB7 * RPB];  // [bin49][t], bank = t%32 (conflict-free)
    __shared__ ulonglong2 pts[JCH / 2];          // 2 points per element, 4 KB

    const int t  = threadIdx.x;
    const int i  = blockIdx.x * RPB + t;
    const int j0 = blockIdx.y * JCH;

    // Stage slice points: 256 x LDS... (128B-aligned float4-equivalent loads)
    {
        const ulonglong2* src = (const ulonglong2*)(obs2 + 2 * j0);
#pragma unroll
        for (int k = 0; k < JCH / 2 / RPB; k++)
            pts[t + k * RPB] = src[t + k * RPB];
    }
    // Zero counters: 49*128 words, 49 per thread
#pragma unroll
    for (int k = 0; k < NB7 * NB7; k++)
        cnt[k * RPB + t] = 0u;

    const float2 pi = ((const float2*)obs2)[i];
    float nx = -pi.x, ny = -pi.y;
    unsigned long long negpi;
    asm("mov.b64 %0, {%1,%2};" : "=l"(negpi) : "f"(nx), "f"(ny));
    const unsigned long long THREE2 = 0x4040000040400000ULL;  // (3.0f, 3.0f)
    const float MAGIC = 8388608.0f;                           // 2^23

    __syncthreads();

    unsigned* mycnt = cnt + t;

#pragma unroll 4
    for (int k = 0; k < JCH / 2; k++) {
        const ulonglong2 pp = pts[k];   // LDS.128: two points, warp-uniform
#pragma unroll
        for (int half = 0; half < 2; half++) {
            const unsigned long long pj = half ? pp.y : pp.x;
            unsigned long long d, e;
            // EXACT reference order per lane: rn(pj - pi), then rn(+3)
            asm("add.rn.f32x2 %0, %1, %2;" : "=l"(d) : "l"(pj), "l"(negpi));
            asm("add.rn.f32x2 %0, %1, %2;" : "=l"(e) : "l"(d), "l"(THREE2));
            const float ex = __uint_as_float((unsigned)e);
            const float ey = __uint_as_float((unsigned)(e >> 32));
            float fx, fy;
            asm("add.rm.f32 %0, %1, %2;" : "=f"(fx) : "f"(ex), "f"(MAGIC));
            asm("add.rm.f32 %0, %1, %2;" : "=f"(fy) : "f"(ey), "f"(MAGIC));
            unsigned bx = __float_as_uint(fx) - 0x4B000000u;  // floor; OOR -> huge
            unsigned by = __float_as_uint(fy) - 0x4B000000u;
            bx = umin(bx, 6u);
            by = umin(by, 6u);
            mycnt[(bx * NB7 + by) * RPB] += 1u;  // conflict-free RMW, no branch
        }
    }

    __syncthreads();  // flush reads other threads' counter columns

    // Flush 36 valid bins as u16-packed row pairs: 36*64 = 2304 words, 18/thread.
    const int sl = blockIdx.y;
#pragma unroll
    for (int k = 0; k < 18; k++) {
        const int gidx = k * RPB + t;     // 0..2303
        const int vb   = gidx >> 6;       // valid bin 0..35
        const int w    = gidx & 63;       // row-pair within block
        const int b49  = (vb / GN) * NB7 + (vb % GN);
        const unsigned lo = cnt[b49 * RPB + 2 * w];
        const unsigned hi = cnt[b49 * RPB + 2 * w + 1];
        g_part[(sl * NN + vb) * HROW + ((blockIdx.x * RPB) >> 1) + w] = lo | (hi << 16);
    }
}

// ---------------------------------------------------------------------------
// Phase 2: reduce slices (packed u16 adds), remove self pair (bin 21),
// linear embedding. 1024 blocks x 128 thr: block = 8 rows x 128 h.
// ---------------------------------------------------------------------------
__global__ __launch_bounds__(HID) void embed_kernel(const float* __restrict__ W,
                                                    const float* __restrict__ b,
                                                    float* __restrict__ out) {
    __shared__ float cs[8][NN];   // reduced counts for this block's 8 rows

    const int t  = threadIdx.x;
    const int i0 = blockIdx.x * 8;

    // 36 bins x 4 row-pair words = 144 reduction tasks
    for (int task = t; task < NN * 4; task += HID) {
        const int c = task >> 2;
        const int w = task & 3;
        const unsigned* p = &g_part[c * HROW + (i0 >> 1) + w];
        unsigned s = 0;
#pragma unroll
        for (int sl = 0; sl < NSL; sl++)
            s += p[sl * NN * HROW];       // packed u16 pair add (max 8192, no carry)
        const unsigned self = (c == 3 * GN + 3) ? 1u : 0u;
        cs[2 * w + 0][c] = (float)((s & 0xFFFFu) - self);
        cs[2 * w + 1][c] = (float)((s >> 16) - self);
    }
    __syncthreads();

    // One thread per h: W row = 36 consecutive floats = 9 float4 (144B, 16B-aligned)
    const int h = t;
    float w[NN];
    {
        const float4* Wv = (const float4*)(W + h * NN);
#pragma unroll
        for (int q = 0; q < NN / 4; q++) {
            const float4 v = Wv[q];
            w[4 * q + 0] = v.x; w[4 * q + 1] = v.y;
            w[4 * q + 2] = v.z; w[4 * q + 3] = v.w;
        }
    }
    const float bh = b[h];

#pragma unroll
    for (int r = 0; r < 8; r++) {
        float acc = bh;
#pragma unroll
        for (int c = 0; c < NN; c++)
            acc = fmaf(cs[r][c], w[c], acc);   // cs broadcast LDS
        out[(i0 + r) * HID + h] = acc;         // coalesced
    }
}

// ---------------------------------------------------------------------------
// Inputs: 0 hidden_state (unused), 1 obs1 (unused), 2 obs2 [8192,2],
// 3 W [128,36], 4 b [128]. Output fp32 [8192,128].
// ---------------------------------------------------------------------------
extern "C" void kernel_launch(void* const* d_in, const int* in_sizes, int n_in,
                              void* d_out, int out_size) {
    const float* obs2 = (const float*)d_in[2];
    const float* W    = (const float*)d_in[3];
    const float* b    = (const float*)d_in[4];
    float*       out  = (float*)d_out;

    dim3 g1(NPED / RPB, NSL);        // 64 x 16 = 1024 blocks
    count_kernel<<<g1, RPB>>>(obs2);
    embed_kernel<<<NPED / 8, HID>>>(W, b, out);
}